// round 3
// baseline (speedup 1.0000x reference)
#include <cuda_runtime.h>
#include <cstdint>

#define NN 100000
#define EE 3200000
#define F  128
#define NG 64
#define NO 10

// ---------------- scratch (static device globals; no runtime allocation) ----
__device__ float g_h[(size_t)NN * F];     // activations
__device__ float g_t[(size_t)NN * F];     // h @ W scratch
__device__ float g_dis[NN];               // rsqrt(deg)
__device__ int   g_cnt[NN];               // per-dst real-edge count
__device__ int   g_rowptr[NN];
__device__ int   g_cursor[NN];
__device__ int   g_col[EE];               // CSR src indices
__device__ float g_eval[EE];              // dis[src] per CSR slot
__device__ float g_pool[NG * F];
__device__ float g_pcnt[NG];
__device__ int   g_part[128];             // scan partials
__device__ int   g_is64;                  // 1 if index arrays are int64

// load logical element i from an index array of unknown width
__device__ __forceinline__ int load_idx(const void* p, size_t i, int is64) {
    if (is64) return (int)((const long long*)p)[i];
    return ((const int*)p)[i];
}

// ---------------- dtype detection ----------------
// If edge_index is int64 with values < 2^31, every odd int32 word is 0.
__global__ void k_detect(const int* __restrict__ ei32) {
    if (threadIdx.x == 0) {
        int all0 = 1;
        #pragma unroll
        for (int j = 0; j < 64; j++)
            if (ei32[2 * j + 1] != 0) all0 = 0;
        g_is64 = all0;
    }
}

// ---------------- init / degree / CSR ----------------
__global__ void k_zero() {
    int i = blockIdx.x * blockDim.x + threadIdx.x;
    if (i < NN) g_cnt[i] = 0;
    if (i < NG * F) g_pool[i] = 0.f;
    if (i < NG) g_pcnt[i] = 0.f;
}

__global__ void k_deg(const void* __restrict__ ei) {
    int e = blockIdx.x * blockDim.x + threadIdx.x;
    int is64 = g_is64;
    if (e < EE) {
        int d = load_idx(ei, (size_t)EE + e, is64);
        atomicAdd(&g_cnt[d], 1);
    }
}

__global__ void k_dis() {
    int i = blockIdx.x * blockDim.x + threadIdx.x;
    if (i < NN) g_dis[i] = rsqrtf((float)g_cnt[i] + 1.0f);  // +1 self loop
}

__global__ void k_scan1() {
    __shared__ int s[1024];
    int t = threadIdx.x;
    int i = blockIdx.x * 1024 + t;
    int v = (i < NN) ? g_cnt[i] : 0;
    s[t] = v;
    __syncthreads();
    for (int off = 1; off < 1024; off <<= 1) {
        int x = (t >= off) ? s[t - off] : 0;
        __syncthreads();
        s[t] += x;
        __syncthreads();
    }
    if (i < NN) g_rowptr[i] = s[t] - v;          // local exclusive
    if (t == 1023) g_part[blockIdx.x] = s[1023]; // block total
}

__global__ void k_scan2(int nblk) {
    __shared__ int p[128];
    int t = threadIdx.x;
    int v = (t < nblk) ? g_part[t] : 0;
    p[t] = v;
    __syncthreads();
    for (int off = 1; off < 128; off <<= 1) {
        int x = (t >= off) ? p[t - off] : 0;
        __syncthreads();
        p[t] += x;
        __syncthreads();
    }
    if (t < nblk) g_part[t] = p[t] - v;          // exclusive offsets
}

__global__ void k_scan3() {
    int i = blockIdx.x * blockDim.x + threadIdx.x;
    if (i < NN) {
        int v = g_rowptr[i] + g_part[i >> 10];
        g_rowptr[i] = v;
        g_cursor[i] = v;
    }
}

__global__ void k_scatter(const void* __restrict__ ei) {
    int e = blockIdx.x * blockDim.x + threadIdx.x;
    int is64 = g_is64;
    if (e < EE) {
        int s = load_idx(ei, e, is64);
        int d = load_idx(ei, (size_t)EE + e, is64);
        int pos = atomicAdd(&g_cursor[d], 1);
        g_col[pos]  = s;
        g_eval[pos] = g_dis[s];
    }
}

// ---------------- GEMM: out = act(A[M,128] @ W[128,128] (+bias)) ------------
// 256 threads = 8 groups x 32 lanes; group handles 4 rows, lane 4 cols.
// sel==0: A = x (external), out = g_h, +bias +relu
// sel==1: A = g_h,          out = g_t, no epilogue
__global__ __launch_bounds__(256) void k_gemm(
    const float* __restrict__ A_ext, const float* __restrict__ W,
    const float* __restrict__ bias, int sel)
{
    __shared__ float As[32 * F];   // 16 KB
    const float* A = sel ? g_h : A_ext;
    float* outp    = sel ? g_t : g_h;

    int tid = threadIdx.x;
    int grp = tid >> 5, lane = tid & 31;
    int col = lane * 4;
    float4 b4 = make_float4(0.f, 0.f, 0.f, 0.f);
    if (!sel) b4 = ((const float4*)bias)[lane];

    for (int t0 = blockIdx.x * 32; t0 < NN; t0 += gridDim.x * 32) {
        for (int i = tid; i < 32 * F; i += 256) {
            int r = t0 + (i >> 7);
            As[i] = (r < NN) ? A[(size_t)r * F + (i & 127)] : 0.f;
        }
        __syncthreads();
        int rb = grp * 4;
        float4 a0 = make_float4(0,0,0,0), a1 = a0, a2 = a0, a3 = a0;
        #pragma unroll 8
        for (int k = 0; k < F; k++) {
            float4 w = __ldg((const float4*)&W[k * F + col]);
            float x0 = As[(rb + 0) * F + k];
            float x1 = As[(rb + 1) * F + k];
            float x2 = As[(rb + 2) * F + k];
            float x3 = As[(rb + 3) * F + k];
            a0.x += x0 * w.x; a0.y += x0 * w.y; a0.z += x0 * w.z; a0.w += x0 * w.w;
            a1.x += x1 * w.x; a1.y += x1 * w.y; a1.z += x1 * w.z; a1.w += x1 * w.w;
            a2.x += x2 * w.x; a2.y += x2 * w.y; a2.z += x2 * w.z; a2.w += x2 * w.w;
            a3.x += x3 * w.x; a3.y += x3 * w.y; a3.z += x3 * w.z; a3.w += x3 * w.w;
        }
        float4 accs[4] = {a0, a1, a2, a3};
        #pragma unroll
        for (int r = 0; r < 4; r++) {
            int row = t0 + rb + r;
            if (row < NN) {
                float4 v = accs[r];
                if (!sel) {
                    v.x = fmaxf(v.x + b4.x, 0.f);
                    v.y = fmaxf(v.y + b4.y, 0.f);
                    v.z = fmaxf(v.z + b4.z, 0.f);
                    v.w = fmaxf(v.w + b4.w, 0.f);
                }
                ((float4*)outp)[(size_t)row * 32 + lane] = v;
            }
        }
        __syncthreads();
    }
}

// ---------------- SpMM: g_h[d] = relu(dis[d]*sum + dis[d]^2*g_t[d] + b) -----
__global__ __launch_bounds__(256) void k_spmm(const float* __restrict__ bias)
{
    int w = (blockIdx.x * blockDim.x + threadIdx.x) >> 5;
    int lane = threadIdx.x & 31;
    if (w >= NN) return;
    const float* hw = g_t;
    int start = g_rowptr[w];
    int c = g_cnt[w];
    float dd = g_dis[w];
    float4 acc = make_float4(0.f, 0.f, 0.f, 0.f);
    for (int j0 = 0; j0 < c; j0 += 32) {
        int idx = j0 + lane;
        int src = 0; float ev = 0.f;
        if (idx < c) { src = g_col[start + idx]; ev = g_eval[start + idx]; }
        int m = min(32, c - j0);
        #pragma unroll 4
        for (int t = 0; t < m; t++) {
            int ss = __shfl_sync(0xffffffffu, src, t);
            float wv = __shfl_sync(0xffffffffu, ev, t);
            float4 v = *(const float4*)(hw + (size_t)ss * F + lane * 4);
            acc.x += wv * v.x; acc.y += wv * v.y;
            acc.z += wv * v.z; acc.w += wv * v.w;
        }
    }
    float4 hv = *(const float4*)(hw + (size_t)w * F + lane * 4);
    float4 b4 = ((const float4*)bias)[lane];
    float sl = dd * dd;
    float4 o;
    o.x = fmaxf(dd * acc.x + sl * hv.x + b4.x, 0.f);
    o.y = fmaxf(dd * acc.y + sl * hv.y + b4.y, 0.f);
    o.z = fmaxf(dd * acc.z + sl * hv.z + b4.z, 0.f);
    o.w = fmaxf(dd * acc.w + sl * hv.w + b4.w, 0.f);
    ((float4*)g_h)[(size_t)w * 32 + lane] = o;
}

// ---------------- pooling (batch sorted -> register accumulation) ----------
__global__ __launch_bounds__(256) void k_pool(const void* __restrict__ batch)
{
    int w = (blockIdx.x * blockDim.x + threadIdx.x) >> 5;
    int lane = threadIdx.x & 31;
    int n0 = w * 64;
    if (n0 >= NN) return;
    int is64 = g_is64;
    int n1 = min(n0 + 64, NN);
    float4 acc = make_float4(0.f, 0.f, 0.f, 0.f);
    int cn = 0;
    int cur = load_idx(batch, n0, is64);
    for (int node = n0; node < n1; node++) {
        int g = load_idx(batch, node, is64);
        if (g != cur) {
            atomicAdd(&g_pool[cur * F + lane * 4 + 0], acc.x);
            atomicAdd(&g_pool[cur * F + lane * 4 + 1], acc.y);
            atomicAdd(&g_pool[cur * F + lane * 4 + 2], acc.z);
            atomicAdd(&g_pool[cur * F + lane * 4 + 3], acc.w);
            if (lane == 0) atomicAdd(&g_pcnt[cur], (float)cn);
            acc = make_float4(0.f, 0.f, 0.f, 0.f); cn = 0; cur = g;
        }
        float4 v = ((const float4*)g_h)[(size_t)node * 32 + lane];
        acc.x += v.x; acc.y += v.y; acc.z += v.z; acc.w += v.w;
        cn++;
    }
    atomicAdd(&g_pool[cur * F + lane * 4 + 0], acc.x);
    atomicAdd(&g_pool[cur * F + lane * 4 + 1], acc.y);
    atomicAdd(&g_pool[cur * F + lane * 4 + 2], acc.z);
    atomicAdd(&g_pool[cur * F + lane * 4 + 3], acc.w);
    if (lane == 0) atomicAdd(&g_pcnt[cur], (float)cn);
}

// ---------------- classifier: out[64,10] = (pool/cnt) @ Wcls + bcls --------
__global__ void k_final(const float* __restrict__ Wc,
                        const float* __restrict__ bc, float* __restrict__ outp)
{
    int t = threadIdx.x;
    if (t >= NG * NO) return;
    int g = t / NO, o = t % NO;
    float inv = 1.f / fmaxf(g_pcnt[g], 1.f);
    float s = 0.f;
    #pragma unroll 8
    for (int k = 0; k < F; k++) s += g_pool[g * F + k] * Wc[k * NO + o];
    outp[t] = s * inv + bc[o];
}

// ---------------- launch (kernel launches ONLY; graph-capture safe) --------
extern "C" void kernel_launch(void* const* d_in, const int* in_sizes, int n_in,
                              void* d_out, int out_size)
{
    const float* x     = (const float*)d_in[0];
    const void*  ei    = d_in[1];
    const void*  batch = d_in[2];
    const float* W_pre = (const float*)d_in[3];
    const float* b_pre = (const float*)d_in[4];
    const float* Wl[3] = {(const float*)d_in[5], (const float*)d_in[7], (const float*)d_in[9]};
    const float* bl[3] = {(const float*)d_in[6], (const float*)d_in[8], (const float*)d_in[10]};
    const float* Wcls  = (const float*)d_in[11];
    const float* bcls  = (const float*)d_in[12];
    float* outp = (float*)d_out;

    int nblkN = (NN + 255) / 256;           // 391
    int nblkE = (EE + 255) / 256;           // 12500
    int nScan = (NN + 1023) / 1024;         // 98

    k_detect<<<1, 32>>>((const int*)ei);
    k_zero<<<nblkN, 256>>>();
    k_deg<<<nblkE, 256>>>(ei);
    k_dis<<<nblkN, 256>>>();
    k_scan1<<<nScan, 1024>>>();
    k_scan2<<<1, 128>>>(nScan);
    k_scan3<<<nblkN, 256>>>();
    k_scatter<<<nblkE, 256>>>(ei);

    // pre-layer: g_h = relu(x @ W_pre + b_pre)
    k_gemm<<<592, 256>>>(x, W_pre, b_pre, 0);

    // 3 GCN conv layers: g_t = g_h @ Wl; g_h = relu(aggregate(g_t) + bl)
    int spmmBlk = (NN * 32 + 255) / 256;    // 12500
    for (int l = 0; l < 3; l++) {
        k_gemm<<<592, 256>>>(nullptr, Wl[l], nullptr, 1);
        k_spmm<<<spmmBlk, 256>>>(bl[l]);
    }

    // mean pool + classifier
    int poolBlk = ((NN + 63) / 64 * 32 + 255) / 256; // 196
    k_pool<<<poolBlk, 256>>>(batch);
    k_final<<<1, NG * NO>>>(Wcls, bcls, outp);
}

// round 4
// speedup vs baseline: 1.2982x; 1.2982x over previous
#include <cuda_runtime.h>
#include <cuda_bf16.h>
#include <cstdint>

#define NN 100000
#define EE 3200000
#define F  128
#define NG 64
#define NO 10

typedef unsigned long long ull;

// ---------------- scratch (static device globals) ----------------
__device__ float g_h[(size_t)NN * F];            // fp32 activations
__device__ __nv_bfloat16 g_tb[(size_t)NN * F];   // bf16 h@W (gather table)
__device__ float g_dis[NN];
__device__ int   g_cnt[NN];
__device__ int   g_rowptr[NN];
__device__ int   g_cursor[NN];
__device__ int2  g_ce[EE];                        // {src, dis[src] bits}
__device__ float g_pool[NG * F];
__device__ float g_pcnt[NG];
__device__ int   g_part[128];
__device__ int   g_is64;

__device__ __forceinline__ int load_idx(const void* p, size_t i, int is64) {
    if (is64) return (int)((const long long*)p)[i];
    return ((const int*)p)[i];
}

#define FMA2(acc, a, b) asm("fma.rn.f32x2 %0, %1, %2, %0;" : "+l"(acc) : "l"(a), "l"(b))
#define PACK2(d, s)     asm("mov.b64 %0, {%1, %1};" : "=l"(d) : "f"(s))
#define UNPACK2(lo, hi, s) asm("mov.b64 {%0, %1}, %2;" : "=f"(lo), "=f"(hi) : "l"(s))
#define CVTBF2(d, hi, lo) asm("cvt.rn.bf16x2.f32 %0, %1, %2;" : "=r"(d) : "f"(hi), "f"(lo))

// ---------------- dtype detection ----------------
__global__ void k_detect(const int* __restrict__ ei32) {
    if (threadIdx.x == 0) {
        int all0 = 1;
        #pragma unroll
        for (int j = 0; j < 64; j++)
            if (ei32[2 * j + 1] != 0) all0 = 0;
        g_is64 = all0;
    }
}

// ---------------- init / degree / CSR ----------------
__global__ void k_zero() {
    int i = blockIdx.x * blockDim.x + threadIdx.x;
    if (i < NN) g_cnt[i] = 0;
    if (i < NG * F) g_pool[i] = 0.f;
    if (i < NG) g_pcnt[i] = 0.f;
}

__global__ void k_deg(const void* __restrict__ ei) {
    int e = blockIdx.x * blockDim.x + threadIdx.x;
    int is64 = g_is64;
    if (e < EE) {
        int d = load_idx(ei, (size_t)EE + e, is64);
        atomicAdd(&g_cnt[d], 1);
    }
}

__global__ void k_dis() {
    int i = blockIdx.x * blockDim.x + threadIdx.x;
    if (i < NN) g_dis[i] = rsqrtf((float)g_cnt[i] + 1.0f);
}

__global__ void k_scan1() {
    __shared__ int s[1024];
    int t = threadIdx.x;
    int i = blockIdx.x * 1024 + t;
    int v = (i < NN) ? g_cnt[i] : 0;
    s[t] = v;
    __syncthreads();
    for (int off = 1; off < 1024; off <<= 1) {
        int x = (t >= off) ? s[t - off] : 0;
        __syncthreads();
        s[t] += x;
        __syncthreads();
    }
    if (i < NN) g_rowptr[i] = s[t] - v;
    if (t == 1023) g_part[blockIdx.x] = s[1023];
}

__global__ void k_scan2(int nblk) {
    __shared__ int p[128];
    int t = threadIdx.x;
    int v = (t < nblk) ? g_part[t] : 0;
    p[t] = v;
    __syncthreads();
    for (int off = 1; off < 128; off <<= 1) {
        int x = (t >= off) ? p[t - off] : 0;
        __syncthreads();
        p[t] += x;
        __syncthreads();
    }
    if (t < nblk) g_part[t] = p[t] - v;
}

__global__ void k_scan3() {
    int i = blockIdx.x * blockDim.x + threadIdx.x;
    if (i < NN) {
        int v = g_rowptr[i] + g_part[i >> 10];
        g_rowptr[i] = v;
        g_cursor[i] = v;
    }
}

__global__ void k_scatter(const void* __restrict__ ei) {
    int e = blockIdx.x * blockDim.x + threadIdx.x;
    int is64 = g_is64;
    if (e < EE) {
        int s = load_idx(ei, e, is64);
        int d = load_idx(ei, (size_t)EE + e, is64);
        int pos = atomicAdd(&g_cursor[d], 1);
        g_ce[pos] = make_int2(s, __float_as_int(g_dis[s]));
    }
}

// ---------------- GEMM: 64-row tile, f32x2 FMA, transposed A in smem -------
// sel==0: out = relu(x @ W + bias) -> g_h (fp32)
// sel==1: out = g_h @ W            -> g_tb (bf16)
__global__ __launch_bounds__(256) void k_gemm(
    const float* __restrict__ A_ext, const float* __restrict__ W,
    const float* __restrict__ bias, int sel)
{
    __shared__ __align__(16) float As[F * 66];  // transposed: As[k*66 + row]
    const float4* Af = (const float4*)(sel ? (const float*)g_h : A_ext);
    int tid = threadIdx.x;
    int t0 = blockIdx.x * 64;

    // load tile transposed (coalesced global, conflict-light smem stores)
    {
        int row = tid >> 2, c4b = tid & 3;
        int gr = t0 + row;
        #pragma unroll
        for (int j = 0; j < 8; j++) {
            int c4 = c4b + j * 4;
            float4 v = make_float4(0.f, 0.f, 0.f, 0.f);
            if (gr < NN) v = Af[(size_t)gr * 32 + c4];
            As[(c4 * 4 + 0) * 66 + row] = v.x;
            As[(c4 * 4 + 1) * 66 + row] = v.y;
            As[(c4 * 4 + 2) * 66 + row] = v.z;
            As[(c4 * 4 + 3) * 66 + row] = v.w;
        }
    }
    __syncthreads();

    int grp = tid >> 5, lane = tid & 31;
    int rb = grp * 8, col = lane * 4;

    ull acc[4][4];
    #pragma unroll
    for (int p = 0; p < 4; p++)
        #pragma unroll
        for (int c = 0; c < 4; c++) acc[p][c] = 0ull;

    #pragma unroll 4
    for (int k = 0; k < F; k++) {
        float4 w4 = __ldg((const float4*)(W + k * F + col));
        ull w2[4];
        PACK2(w2[0], w4.x); PACK2(w2[1], w4.y);
        PACK2(w2[2], w4.z); PACK2(w2[3], w4.w);
        const ull* xs = (const ull*)&As[k * 66 + rb];
        ull x0 = xs[0], x1 = xs[1], x2 = xs[2], x3 = xs[3];
        #pragma unroll
        for (int c = 0; c < 4; c++) {
            FMA2(acc[0][c], x0, w2[c]);
            FMA2(acc[1][c], x1, w2[c]);
            FMA2(acc[2][c], x2, w2[c]);
            FMA2(acc[3][c], x3, w2[c]);
        }
    }

    float4 b4 = make_float4(0.f, 0.f, 0.f, 0.f);
    if (!sel) b4 = ((const float4*)bias)[lane];

    #pragma unroll
    for (int p = 0; p < 4; p++) {
        float lo[4], hi[4];
        UNPACK2(lo[0], hi[0], acc[p][0]);
        UNPACK2(lo[1], hi[1], acc[p][1]);
        UNPACK2(lo[2], hi[2], acc[p][2]);
        UNPACK2(lo[3], hi[3], acc[p][3]);
        int r0 = t0 + rb + 2 * p;
        if (sel) {
            if (r0 < NN) {
                uint2 u;
                CVTBF2(u.x, lo[1], lo[0]);
                CVTBF2(u.y, lo[3], lo[2]);
                ((uint2*)g_tb)[(size_t)r0 * 32 + lane] = u;
            }
            if (r0 + 1 < NN) {
                uint2 u;
                CVTBF2(u.x, hi[1], hi[0]);
                CVTBF2(u.y, hi[3], hi[2]);
                ((uint2*)g_tb)[(size_t)(r0 + 1) * 32 + lane] = u;
            }
        } else {
            if (r0 < NN) {
                float4 v = make_float4(fmaxf(lo[0] + b4.x, 0.f), fmaxf(lo[1] + b4.y, 0.f),
                                       fmaxf(lo[2] + b4.z, 0.f), fmaxf(lo[3] + b4.w, 0.f));
                ((float4*)g_h)[(size_t)r0 * 32 + lane] = v;
            }
            if (r0 + 1 < NN) {
                float4 v = make_float4(fmaxf(hi[0] + b4.x, 0.f), fmaxf(hi[1] + b4.y, 0.f),
                                       fmaxf(hi[2] + b4.z, 0.f), fmaxf(hi[3] + b4.w, 0.f));
                ((float4*)g_h)[(size_t)(r0 + 1) * 32 + lane] = v;
            }
        }
    }
}

// decode bf16 pair -> two fp32 (exact, ALU-only)
__device__ __forceinline__ void bf2f(unsigned u, float& f0, float& f1) {
    f0 = __int_as_float((int)(u << 16));
    f1 = __int_as_float((int)(u & 0xffff0000u));
}

// ---------------- SpMM: g_h[d] = relu(dis[d]*sum + dis[d]^2*hW[d] + b) -----
__global__ __launch_bounds__(256) void k_spmm(const float* __restrict__ bias)
{
    int w = (blockIdx.x * blockDim.x + threadIdx.x) >> 5;
    int lane = threadIdx.x & 31;
    if (w >= NN) return;
    int start = g_rowptr[w];
    int c = g_cnt[w];
    float dd = g_dis[w];
    float4 acc = make_float4(0.f, 0.f, 0.f, 0.f);
    const uint2* tb = (const uint2*)g_tb;
    for (int j0 = 0; j0 < c; j0 += 32) {
        int idx = j0 + lane;
        int2 ce = make_int2(0, 0);
        if (idx < c) ce = g_ce[start + idx];
        int m = min(32, c - j0);
        #pragma unroll 4
        for (int t = 0; t < m; t++) {
            int ss   = __shfl_sync(0xffffffffu, ce.x, t);
            float wv = __int_as_float(__shfl_sync(0xffffffffu, ce.y, t));
            uint2 u = tb[(size_t)ss * 32 + lane];
            float f0, f1, f2, f3;
            bf2f(u.x, f0, f1); bf2f(u.y, f2, f3);
            acc.x += wv * f0; acc.y += wv * f1;
            acc.z += wv * f2; acc.w += wv * f3;
        }
    }
    uint2 su = tb[(size_t)w * 32 + lane];
    float h0, h1, h2, h3;
    bf2f(su.x, h0, h1); bf2f(su.y, h2, h3);
    float4 b4 = ((const float4*)bias)[lane];
    float sl = dd * dd;
    float4 o;
    o.x = fmaxf(dd * acc.x + sl * h0 + b4.x, 0.f);
    o.y = fmaxf(dd * acc.y + sl * h1 + b4.y, 0.f);
    o.z = fmaxf(dd * acc.z + sl * h2 + b4.z, 0.f);
    o.w = fmaxf(dd * acc.w + sl * h3 + b4.w, 0.f);
    ((float4*)g_h)[(size_t)w * 32 + lane] = o;
}

// ---------------- pooling ----------------
__global__ __launch_bounds__(256) void k_pool(const void* __restrict__ batch)
{
    int w = (blockIdx.x * blockDim.x + threadIdx.x) >> 5;
    int lane = threadIdx.x & 31;
    int n0 = w * 64;
    if (n0 >= NN) return;
    int is64 = g_is64;
    int n1 = min(n0 + 64, NN);
    float4 acc = make_float4(0.f, 0.f, 0.f, 0.f);
    int cn = 0;
    int cur = load_idx(batch, n0, is64);
    for (int node = n0; node < n1; node++) {
        int g = load_idx(batch, node, is64);
        if (g != cur) {
            atomicAdd(&g_pool[cur * F + lane * 4 + 0], acc.x);
            atomicAdd(&g_pool[cur * F + lane * 4 + 1], acc.y);
            atomicAdd(&g_pool[cur * F + lane * 4 + 2], acc.z);
            atomicAdd(&g_pool[cur * F + lane * 4 + 3], acc.w);
            if (lane == 0) atomicAdd(&g_pcnt[cur], (float)cn);
            acc = make_float4(0.f, 0.f, 0.f, 0.f); cn = 0; cur = g;
        }
        float4 v = ((const float4*)g_h)[(size_t)node * 32 + lane];
        acc.x += v.x; acc.y += v.y; acc.z += v.z; acc.w += v.w;
        cn++;
    }
    atomicAdd(&g_pool[cur * F + lane * 4 + 0], acc.x);
    atomicAdd(&g_pool[cur * F + lane * 4 + 1], acc.y);
    atomicAdd(&g_pool[cur * F + lane * 4 + 2], acc.z);
    atomicAdd(&g_pool[cur * F + lane * 4 + 3], acc.w);
    if (lane == 0) atomicAdd(&g_pcnt[cur], (float)cn);
}

// ---------------- classifier ----------------
__global__ void k_final(const float* __restrict__ Wc,
                        const float* __restrict__ bc, float* __restrict__ outp)
{
    int t = threadIdx.x;
    if (t >= NG * NO) return;
    int g = t / NO, o = t % NO;
    float inv = 1.f / fmaxf(g_pcnt[g], 1.f);
    float s = 0.f;
    #pragma unroll 8
    for (int k = 0; k < F; k++) s += g_pool[g * F + k] * Wc[k * NO + o];
    outp[t] = s * inv + bc[o];
}

// ---------------- launch ----------------
extern "C" void kernel_launch(void* const* d_in, const int* in_sizes, int n_in,
                              void* d_out, int out_size)
{
    const float* x     = (const float*)d_in[0];
    const void*  ei    = d_in[1];
    const void*  batch = d_in[2];
    const float* W_pre = (const float*)d_in[3];
    const float* b_pre = (const float*)d_in[4];
    const float* Wl[3] = {(const float*)d_in[5], (const float*)d_in[7], (const float*)d_in[9]};
    const float* bl[3] = {(const float*)d_in[6], (const float*)d_in[8], (const float*)d_in[10]};
    const float* Wcls  = (const float*)d_in[11];
    const float* bcls  = (const float*)d_in[12];
    float* outp = (float*)d_out;

    int nblkN = (NN + 255) / 256;
    int nblkE = (EE + 255) / 256;
    int nScan = (NN + 1023) / 1024;

    k_detect<<<1, 32>>>((const int*)ei);
    k_zero<<<nblkN, 256>>>();
    k_deg<<<nblkE, 256>>>(ei);
    k_dis<<<nblkN, 256>>>();
    k_scan1<<<nScan, 1024>>>();
    k_scan2<<<1, 128>>>(nScan);
    k_scan3<<<nblkN, 256>>>();
    k_scatter<<<nblkE, 256>>>(ei);

    int gemmBlk = (NN + 63) / 64;           // 1563
    k_gemm<<<gemmBlk, 256>>>(x, W_pre, b_pre, 0);

    int spmmBlk = (NN * 32 + 255) / 256;    // 12500
    for (int l = 0; l < 3; l++) {
        k_gemm<<<gemmBlk, 256>>>(nullptr, Wl[l], nullptr, 1);
        k_spmm<<<spmmBlk, 256>>>(bl[l]);
    }

    int poolBlk = ((NN + 63) / 64 * 32 + 255) / 256;
    k_pool<<<poolBlk, 256>>>(batch);
    k_final<<<1, NG * NO>>>(Wcls, bcls, outp);
}

// round 7
// speedup vs baseline: 1.4320x; 1.1031x over previous
#include <cuda_runtime.h>
#include <cuda_bf16.h>
#include <cstdint>

#define NN 100000
#define EE 3200000
#define F  128
#define NG 64
#define NO 10

typedef unsigned long long ull;

// ---------------- scratch (static device globals) ----------------
__device__ float g_h[(size_t)NN * F];            // fp32 activations
__device__ __nv_bfloat16 g_tb[(size_t)NN * F];   // bf16 h@W (gather table)
__device__ float g_dis[NN];
__device__ int   g_cnt[NN];
__device__ int   g_rowptr[NN];
__device__ int   g_cursor[NN];
__device__ int2  g_ce[EE];                        // {src, dis[src] bits}
__device__ float g_pool[NG * F];
__device__ float g_pcnt[NG];
__device__ int   g_part[128];
__device__ int   g_is64;

__device__ __forceinline__ int load_idx(const void* p, size_t i, int is64) {
    if (is64) return (int)((const long long*)p)[i];
    return ((const int*)p)[i];
}

#define FMA2(acc, a, b) asm("fma.rn.f32x2 %0, %1, %2, %0;" : "+l"(acc) : "l"(a), "l"(b))
#define PACK2(d, s)     asm("mov.b64 %0, {%1, %1};" : "=l"(d) : "f"(s))
#define UNPACK2(lo, hi, s) asm("mov.b64 {%0, %1}, %2;" : "=f"(lo), "=f"(hi) : "l"(s))
#define CVTBF2(d, hi, lo) asm("cvt.rn.bf16x2.f32 %0, %1, %2;" : "=r"(d) : "f"(hi), "f"(lo))

// ---------------- dtype detection ----------------
__global__ void k_detect(const int* __restrict__ ei32) {
    if (threadIdx.x == 0) {
        int all0 = 1;
        #pragma unroll
        for (int j = 0; j < 64; j++)
            if (ei32[2 * j + 1] != 0) all0 = 0;
        g_is64 = all0;
    }
}

// ---------------- init / degree / CSR ----------------
__global__ void k_zero() {
    int i = blockIdx.x * blockDim.x + threadIdx.x;
    if (i < NN) g_cnt[i] = 0;
    if (i < NG * F) g_pool[i] = 0.f;
    if (i < NG) g_pcnt[i] = 0.f;
}

__global__ void k_deg(const void* __restrict__ ei) {
    int e = blockIdx.x * blockDim.x + threadIdx.x;
    int is64 = g_is64;
    if (e < EE) {
        int d = load_idx(ei, (size_t)EE + e, is64);
        atomicAdd(&g_cnt[d], 1);
    }
}

__global__ void k_dis() {
    int i = blockIdx.x * blockDim.x + threadIdx.x;
    if (i < NN) g_dis[i] = rsqrtf((float)g_cnt[i] + 1.0f);
}

__global__ void k_scan1() {
    __shared__ int s[1024];
    int t = threadIdx.x;
    int i = blockIdx.x * 1024 + t;
    int v = (i < NN) ? g_cnt[i] : 0;
    s[t] = v;
    __syncthreads();
    for (int off = 1; off < 1024; off <<= 1) {
        int x = (t >= off) ? s[t - off] : 0;
        __syncthreads();
        s[t] += x;
        __syncthreads();
    }
    if (i < NN) g_rowptr[i] = s[t] - v;
    if (t == 1023) g_part[blockIdx.x] = s[1023];
}

__global__ void k_scan2(int nblk) {
    __shared__ int p[128];
    int t = threadIdx.x;
    int v = (t < nblk) ? g_part[t] : 0;
    p[t] = v;
    __syncthreads();
    for (int off = 1; off < 128; off <<= 1) {
        int x = (t >= off) ? p[t - off] : 0;
        __syncthreads();
        p[t] += x;
        __syncthreads();
    }
    if (t < nblk) g_part[t] = p[t] - v;
}

__global__ void k_scan3() {
    int i = blockIdx.x * blockDim.x + threadIdx.x;
    if (i < NN) {
        int v = g_rowptr[i] + g_part[i >> 10];
        g_rowptr[i] = v;
        g_cursor[i] = v;
    }
}

__global__ void k_scatter(const void* __restrict__ ei) {
    int e = blockIdx.x * blockDim.x + threadIdx.x;
    int is64 = g_is64;
    if (e < EE) {
        int s = load_idx(ei, e, is64);
        int d = load_idx(ei, (size_t)EE + e, is64);
        int pos = atomicAdd(&g_cursor[d], 1);
        g_ce[pos] = make_int2(s, __float_as_int(g_dis[s]));
    }
}

// ---------------- GEMM: 64-row tile, f32x2 FMA, transposed A in smem -------
// sel==0: out = relu(x @ W + bias) -> g_h (fp32)
// sel==1: out = g_h @ W            -> g_tb (bf16)
__global__ __launch_bounds__(256) void k_gemm(
    const float* __restrict__ A_ext, const float* __restrict__ W,
    const float* __restrict__ bias, int sel)
{
    __shared__ __align__(16) float As[F * 66];  // transposed: As[k*66 + row]
    const float4* Af = (const float4*)(sel ? (const float*)g_h : A_ext);
    int tid = threadIdx.x;
    int t0 = blockIdx.x * 64;

    // load tile transposed (coalesced global, conflict-light smem stores)
    {
        int row = tid >> 2, c4b = tid & 3;
        int gr = t0 + row;
        #pragma unroll
        for (int j = 0; j < 8; j++) {
            int c4 = c4b + j * 4;
            float4 v = make_float4(0.f, 0.f, 0.f, 0.f);
            if (gr < NN) v = Af[(size_t)gr * 32 + c4];
            As[(c4 * 4 + 0) * 66 + row] = v.x;
            As[(c4 * 4 + 1) * 66 + row] = v.y;
            As[(c4 * 4 + 2) * 66 + row] = v.z;
            As[(c4 * 4 + 3) * 66 + row] = v.w;
        }
    }
    __syncthreads();

    int grp = tid >> 5, lane = tid & 31;
    int rb = grp * 8, col = lane * 4;

    ull acc[4][4];
    #pragma unroll
    for (int p = 0; p < 4; p++)
        #pragma unroll
        for (int c = 0; c < 4; c++) acc[p][c] = 0ull;

    #pragma unroll 4
    for (int k = 0; k < F; k++) {
        float4 w4 = __ldg((const float4*)(W + k * F + col));
        ull w2[4];
        PACK2(w2[0], w4.x); PACK2(w2[1], w4.y);
        PACK2(w2[2], w4.z); PACK2(w2[3], w4.w);
        const ull* xs = (const ull*)&As[k * 66 + rb];
        ull x0 = xs[0], x1 = xs[1], x2 = xs[2], x3 = xs[3];
        #pragma unroll
        for (int c = 0; c < 4; c++) {
            FMA2(acc[0][c], x0, w2[c]);
            FMA2(acc[1][c], x1, w2[c]);
            FMA2(acc[2][c], x2, w2[c]);
            FMA2(acc[3][c], x3, w2[c]);
        }
    }

    float4 b4 = make_float4(0.f, 0.f, 0.f, 0.f);
    if (!sel) b4 = ((const float4*)bias)[lane];

    #pragma unroll
    for (int p = 0; p < 4; p++) {
        float lo[4], hi[4];
        UNPACK2(lo[0], hi[0], acc[p][0]);
        UNPACK2(lo[1], hi[1], acc[p][1]);
        UNPACK2(lo[2], hi[2], acc[p][2]);
        UNPACK2(lo[3], hi[3], acc[p][3]);
        int r0 = t0 + rb + 2 * p;
        if (sel) {
            if (r0 < NN) {
                uint2 u;
                CVTBF2(u.x, lo[1], lo[0]);
                CVTBF2(u.y, lo[3], lo[2]);
                ((uint2*)g_tb)[(size_t)r0 * 32 + lane] = u;
            }
            if (r0 + 1 < NN) {
                uint2 u;
                CVTBF2(u.x, hi[1], hi[0]);
                CVTBF2(u.y, hi[3], hi[2]);
                ((uint2*)g_tb)[(size_t)(r0 + 1) * 32 + lane] = u;
            }
        } else {
            if (r0 < NN) {
                float4 v = make_float4(fmaxf(lo[0] + b4.x, 0.f), fmaxf(lo[1] + b4.y, 0.f),
                                       fmaxf(lo[2] + b4.z, 0.f), fmaxf(lo[3] + b4.w, 0.f));
                ((float4*)g_h)[(size_t)r0 * 32 + lane] = v;
            }
            if (r0 + 1 < NN) {
                float4 v = make_float4(fmaxf(hi[0] + b4.x, 0.f), fmaxf(hi[1] + b4.y, 0.f),
                                       fmaxf(hi[2] + b4.z, 0.f), fmaxf(hi[3] + b4.w, 0.f));
                ((float4*)g_h)[(size_t)(r0 + 1) * 32 + lane] = v;
            }
        }
    }
}

// decode bf16 pair -> two fp32 (exact, ALU-only)
__device__ __forceinline__ void bf2f(unsigned u, float& f0, float& f1) {
    f0 = __int_as_float((int)(u << 16));
    f1 = __int_as_float((int)(u & 0xffff0000u));
}

// ---------------- SpMM: g_h[d] = relu(dis[d]*sum + dis[d]^2*hW[d] + b) -----
__global__ __launch_bounds__(256) void k_spmm(const float* __restrict__ bias)
{
    int w = (blockIdx.x * blockDim.x + threadIdx.x) >> 5;
    int lane = threadIdx.x & 31;
    if (w >= NN) return;
    int start = g_rowptr[w];
    int c = g_cnt[w];
    float dd = g_dis[w];
    float4 acc = make_float4(0.f, 0.f, 0.f, 0.f);
    const uint2* tb = (const uint2*)g_tb;
    int j = 0;
    // 2 edges per iteration: both uniform edge records fetched before gathers
    for (; j + 2 <= c; j += 2) {
        int2 ce0 = __ldg(&g_ce[start + j]);
        int2 ce1 = __ldg(&g_ce[start + j + 1]);
        uint2 u0 = tb[(size_t)ce0.x * 32 + lane];
        uint2 u1 = tb[(size_t)ce1.x * 32 + lane];
        float wv0 = __int_as_float(ce0.y);
        float wv1 = __int_as_float(ce1.y);
        float f0, f1, f2, f3;
        bf2f(u0.x, f0, f1); bf2f(u0.y, f2, f3);
        acc.x += wv0 * f0; acc.y += wv0 * f1;
        acc.z += wv0 * f2; acc.w += wv0 * f3;
        bf2f(u1.x, f0, f1); bf2f(u1.y, f2, f3);
        acc.x += wv1 * f0; acc.y += wv1 * f1;
        acc.z += wv1 * f2; acc.w += wv1 * f3;
    }
    if (j < c) {
        int2 ce = __ldg(&g_ce[start + j]);
        float wv = __int_as_float(ce.y);
        uint2 u = tb[(size_t)ce.x * 32 + lane];
        float f0, f1, f2, f3;
        bf2f(u.x, f0, f1); bf2f(u.y, f2, f3);
        acc.x += wv * f0; acc.y += wv * f1;
        acc.z += wv * f2; acc.w += wv * f3;
    }
    uint2 su = tb[(size_t)w * 32 + lane];
    float h0, h1, h2, h3;
    bf2f(su.x, h0, h1); bf2f(su.y, h2, h3);
    float4 b4 = ((const float4*)bias)[lane];
    float sl = dd * dd;
    float4 o;
    o.x = fmaxf(dd * acc.x + sl * h0 + b4.x, 0.f);
    o.y = fmaxf(dd * acc.y + sl * h1 + b4.y, 0.f);
    o.z = fmaxf(dd * acc.z + sl * h2 + b4.z, 0.f);
    o.w = fmaxf(dd * acc.w + sl * h3 + b4.w, 0.f);
    ((float4*)g_h)[(size_t)w * 32 + lane] = o;
}

// ---------------- pooling ----------------
__global__ __launch_bounds__(256) void k_pool(const void* __restrict__ batch)
{
    int w = (blockIdx.x * blockDim.x + threadIdx.x) >> 5;
    int lane = threadIdx.x & 31;
    int n0 = w * 64;
    if (n0 >= NN) return;
    int is64 = g_is64;
    int n1 = min(n0 + 64, NN);
    float4 acc = make_float4(0.f, 0.f, 0.f, 0.f);
    int cn = 0;
    int cur = load_idx(batch, n0, is64);
    for (int node = n0; node < n1; node++) {
        int g = load_idx(batch, node, is64);
        if (g != cur) {
            atomicAdd(&g_pool[cur * F + lane * 4 + 0], acc.x);
            atomicAdd(&g_pool[cur * F + lane * 4 + 1], acc.y);
            atomicAdd(&g_pool[cur * F + lane * 4 + 2], acc.z);
            atomicAdd(&g_pool[cur * F + lane * 4 + 3], acc.w);
            if (lane == 0) atomicAdd(&g_pcnt[cur], (float)cn);
            acc = make_float4(0.f, 0.f, 0.f, 0.f); cn = 0; cur = g;
        }
        float4 v = ((const float4*)g_h)[(size_t)node * 32 + lane];
        acc.x += v.x; acc.y += v.y; acc.z += v.z; acc.w += v.w;
        cn++;
    }
    atomicAdd(&g_pool[cur * F + lane * 4 + 0], acc.x);
    atomicAdd(&g_pool[cur * F + lane * 4 + 1], acc.y);
    atomicAdd(&g_pool[cur * F + lane * 4 + 2], acc.z);
    atomicAdd(&g_pool[cur * F + lane * 4 + 3], acc.w);
    if (lane == 0) atomicAdd(&g_pcnt[cur], (float)cn);
}

// ---------------- classifier ----------------
__global__ void k_final(const float* __restrict__ Wc,
                        const float* __restrict__ bc, float* __restrict__ outp)
{
    int t = threadIdx.x;
    if (t >= NG * NO) return;
    int g = t / NO, o = t % NO;
    float inv = 1.f / fmaxf(g_pcnt[g], 1.f);
    float s = 0.f;
    #pragma unroll 8
    for (int k = 0; k < F; k++) s += g_pool[g * F + k] * Wc[k * NO + o];
    outp[t] = s * inv + bc[o];
}

// ---------------- launch ----------------
extern "C" void kernel_launch(void* const* d_in, const int* in_sizes, int n_in,
                              void* d_out, int out_size)
{
    const float* x     = (const float*)d_in[0];
    const void*  ei    = d_in[1];
    const void*  batch = d_in[2];
    const float* W_pre = (const float*)d_in[3];
    const float* b_pre = (const float*)d_in[4];
    const float* Wl[3] = {(const float*)d_in[5], (const float*)d_in[7], (const float*)d_in[9]};
    const float* bl[3] = {(const float*)d_in[6], (const float*)d_in[8], (const float*)d_in[10]};
    const float* Wcls  = (const float*)d_in[11];
    const float* bcls  = (const float*)d_in[12];
    float* outp = (float*)d_out;

    int nblkN = (NN + 255) / 256;
    int nblkE = (EE + 255) / 256;
    int nScan = (NN + 1023) / 1024;

    k_detect<<<1, 32>>>((const int*)ei);
    k_zero<<<nblkN, 256>>>();
    k_deg<<<nblkE, 256>>>(ei);
    k_dis<<<nblkN, 256>>>();
    k_scan1<<<nScan, 1024>>>();
    k_scan2<<<1, 128>>>(nScan);
    k_scan3<<<nblkN, 256>>>();
    k_scatter<<<nblkE, 256>>>(ei);

    int gemmBlk = (NN + 63) / 64;           // 1563
    k_gemm<<<gemmBlk, 256>>>(x, W_pre, b_pre, 0);

    int spmmBlk = (NN * 32 + 255) / 256;    // 12500
    for (int l = 0; l < 3; l++) {
        k_gemm<<<gemmBlk, 256>>>(nullptr, Wl[l], nullptr, 1);
        k_spmm<<<spmmBlk, 256>>>(bl[l]);
    }

    int poolBlk = ((NN + 63) / 64 * 32 + 255) / 256;
    k_pool<<<poolBlk, 256>>>(batch);
    k_final<<<1, NG * NO>>>(Wcls, bcls, outp);
}